// round 17
// baseline (speedup 1.0000x reference)
#include <cuda_runtime.h>
#include <cuda_bf16.h>
#include <stdint.h>

// Exact Euclidean distance transform (matches the Meijster-style reference)
// on a 1536x1536 binary mask. Single fused kernel.
//
// Block = 128 output columns x one 32-row word, 256 threads.
//   Stage 1: per-column 36-bit background strips (rows r0-2..r0+33, bit b ==
//     mask[r0-2+b][col]==0) for 132 columns (incl. +/-2 halo), built directly
//     from the mask: 396 (seg,col) units of 12 coalesced float loads each,
//     looped over 256 threads, into part[3][132] smem (12-bit partials).
//     Out-of-image rows/cols => bit 0 ("no background").
//   Stage 2: each thread owns TWO adjacent columns x 8 rows. 6 strip columns
//     (18 LDS) are shared by the pair's plane computations. Bit-parallel
//     coverage for d^2 in {0,1,2,4,5}; priority-exclusive encode into 3
//     bit-planes; per row a 3-level float-select tree per column, packed into
//     ONE float2 store (no I2F/RSQ per pixel, half the store instructions).
//   Rows with d^2 > 5 (P = 2^-21 per pixel for a random mask, ~1 px/image)
//   fall to an exact search on the float mask under a warp vote, reproducing
//   the reference's BIG = R+C cap. Exact for ANY input.
//
// All quantities (g^2 <= 3072^2, t^2, sums < 2^24) are integers exactly
// representable in fp32.

#define R_DIM 1536
#define C_DIM 1536
#define W_DIM (R_DIM / 32)          // 48 word-rows
#define BIG_I (R_DIM + C_DIM)       // 3072
#define TCOLS 128
#define HCOLS (TCOLS + 4)           // 132 strip columns (+/-2 halo)
#define NUNITS (3 * HCOLS)          // 396 stage-1 (seg,col) units

typedef unsigned long long u64;

// Exact vertical nearest-background distance^2 at (r, k), from the mask.
// Cold path (expected ~1 pixel per image).
__device__ __noinline__ int g2_mask(const float* __restrict__ mask, int r, int k)
{
    for (int t = 0; t < R_DIM; ++t) {
        const int ru = r - t, rd = r + t;
        bool hit = false;
        if (ru >= 0    && mask[ru * C_DIM + k] == 0.0f) hit = true;
        if (rd < R_DIM && mask[rd * C_DIM + k] == 0.0f) hit = true;
        if (hit) return t * t;
        if (ru < 0 && rd >= R_DIM) break;
    }
    return BIG_I * BIG_I;
}

// d^2<=5 coverage planes for one column given its strip and neighbor ORs.
// Strip bit i == row r0-2+i. Outputs: 3 bit-planes + uncovered mask (bit r ==
// row r0+r), where plane index 7 == uncovered.
__device__ __forceinline__ void planes_from_strips(
    u64 S0, u64 T1, u64 T2,
    uint32_t& b0, uint32_t& b1, uint32_t& b2, uint32_t& un)
{
    const uint32_t c0 = (uint32_t)(S0 >> 2);
    const uint32_t D1 = (uint32_t)((S0 >> 1) | (S0 >> 3) | (T1 >> 2));
    const uint32_t D2 = (uint32_t)((T1 >> 1) | (T1 >> 3));
    const uint32_t D4 = (uint32_t)( S0       | (S0 >> 4) | (T2 >> 2));
    const uint32_t D5 = (uint32_t)( T1       | (T1 >> 4) | (T2 >> 1) | (T2 >> 3));

    uint32_t cum = c0;
    const uint32_t E1 = D1 & ~cum;  cum |= D1;
    const uint32_t E2 = D2 & ~cum;  cum |= D2;
    const uint32_t E4 = D4 & ~cum;  cum |= D4;
    const uint32_t E5 = D5 & ~cum;  cum |= D5;
    un = ~cum;

    b0 = E1 | E5 | un;
    b1 = E2 | un;
    b2 = E4 | E5 | un;
}

__device__ __forceinline__ float sel_tree(uint32_t b0, uint32_t b1, uint32_t b2, int r)
{
    const bool t0 = (b0 >> r) & 1;
    const bool t1 = (b1 >> r) & 1;
    const bool t2 = (b2 >> r) & 1;
    // d^2: 0->0, 1->1, 2->sqrt2, 4->2, 5->sqrt5 (7 overwritten by fallback)
    const float hi = t0 ? 2.23606798f : 2.0f;
    const float lo = t1 ? 1.41421356f : (t0 ? 1.0f : 0.0f);
    return t2 ? hi : lo;
}

// 256 threads = 64 column-pairs x 4 row-quarters. grid(12, 48).
__global__ __launch_bounds__(256) void edt_fused(const float* __restrict__ mask,
                                                 float* __restrict__ out)
{
    const int tid = threadIdx.x;
    const int c0b = blockIdx.x * TCOLS;
    const int wi  = blockIdx.y;
    const int r0  = wi * 32;

    __shared__ uint32_t part[3][HCOLS];   // 12-bit strip segments per column

    // ---- stage 1: build 36-bit strips from the mask ----
    const bool interior = (wi > 0) && (wi < W_DIM - 1);
    for (int u = tid; u < NUNITS; u += 256) {
        const int seg  = u / HCOLS;                // 0..2 (12 rows each)
        const int col  = u % HCOLS;                // consecutive threads -> consecutive cols
        const int gcol = c0b - 2 + col;
        const int gc   = min(max(gcol, 0), C_DIM - 1);
        const bool colok = (gcol >= 0) && (gcol < C_DIM);
        const int rbase  = r0 - 2 + seg * 12;

        float v[12];
        if (interior) {
            #pragma unroll
            for (int k = 0; k < 12; ++k)
                v[k] = mask[(rbase + k) * C_DIM + gc];
        } else {
            #pragma unroll
            for (int k = 0; k < 12; ++k) {
                const int rr = rbase + k;
                v[k] = (rr >= 0 && rr < R_DIM) ? mask[rr * C_DIM + gc] : 1.0f;
            }
        }
        uint32_t w = 0;
        #pragma unroll
        for (int k = 0; k < 12; ++k)
            if (v[k] == 0.0f) w |= 1u << k;
        part[seg][col] = colok ? w : 0u;
    }
    __syncthreads();

    // ---- stage 2: two adjacent columns per thread ----
    const int ci = tid & 63;                       // column-pair index
    const int q  = tid >> 6;                       // row-quarter 0..3
    const int sh = q * 8;
    const int j0 = c0b + 2 * ci;
    const int sc = 2 * ci + 2;                     // strip idx of col j0

    u64 st[6];                                     // strips for cols j0-2 .. j0+3
    #pragma unroll
    for (int d = 0; d < 6; ++d) {
        const int s = sc - 2 + d;
        st[d] = (u64)part[0][s] | ((u64)part[1][s] << 12) | ((u64)part[2][s] << 24);
    }

    uint32_t a0, a1, a2, una;
    uint32_t c0p, c1p, c2p, unb;
    planes_from_strips(st[2], st[1] | st[3], st[0] | st[4], a0, a1, a2, una);
    planes_from_strips(st[3], st[2] | st[4], st[1] | st[5], c0p, c1p, c2p, unb);

    const uint32_t A0 = a0 >> sh, A1 = a1 >> sh, A2 = a2 >> sh;
    const uint32_t B0 = c0p >> sh, B1 = c1p >> sh, B2 = c2p >> sh;

    float2* orow2 = reinterpret_cast<float2*>(out + (r0 + sh) * C_DIM + j0);
    #pragma unroll
    for (int r = 0; r < 8; ++r) {
        float2 v2;
        v2.x = sel_tree(A0, A1, A2, r);
        v2.y = sel_tree(B0, B1, B2, r);
        orow2[r * (C_DIM / 2)] = v2;
    }

    // ---- exact fallback for rows with d^2 > 5 (~1 pixel per image) ----
    const uint32_t ua = (una >> sh) & 0xffu;
    const uint32_t ub = (unb >> sh) & 0xffu;
    if (__any_sync(0xffffffffu, (ua | ub) != 0u)) {
        #pragma unroll
        for (int side = 0; side < 2; ++side) {
            uint32_t uncov = side ? ub : ua;
            const int j = j0 + side;
            while (uncov) {
                const int b = __ffs(uncov) - 1;
                uncov &= uncov - 1;
                const int row = r0 + sh + b;
                int best = g2_mask(mask, row, j);
                int t = 1, t2i = 1, inc = 3;
                while (t2i < best) {
                    const int kl = j - t, kr = j + t;
                    if (kl < 0 && kr >= C_DIM) break;
                    if (kl >= 0)     best = min(best, g2_mask(mask, row, kl) + t2i);
                    if (kr < C_DIM)  best = min(best, g2_mask(mask, row, kr) + t2i);
                    t2i += inc; inc += 2; ++t;
                }
                const float f = (float)best;
                out[row * C_DIM + j] = best ? f * __frsqrt_rn(f) : 0.0f;
            }
        }
    }
}

extern "C" void kernel_launch(void* const* d_in, const int* in_sizes, int n_in,
                              void* d_out, int out_size) {
    const float* mask = (const float*)d_in[0];
    float* out = (float*)d_out;

    dim3 egrid(C_DIM / TCOLS, W_DIM);   // (12, 48)
    edt_fused<<<egrid, 256>>>(mask, out);
}